// round 2
// baseline (speedup 1.0000x reference)
#include <cuda_runtime.h>
#include <cuda_fp16.h>
#include <cstdint>

#define DIM 4096
#define BM 128
#define BN 128
#define BK 64
#define KT (DIM / BK)            // 64 k-stages
#define NSTAGE 4
#define STAGE_BYTES 32768        // A 128x128B (16KB) + B 128x128B (16KB)
#define SMEM_SCALE (NSTAGE * STAGE_BYTES)
#define SMEM_BIAS  (SMEM_SCALE + BN * 4)
#define SMEM_BYTES (SMEM_BIAS + BN * 4)   // 132096

// fp16 scratch operands (allocation-free: __device__ globals)
__device__ __half g_xh[(size_t)DIM * DIM];
__device__ __half g_wh[(size_t)DIM * DIM];

// ---------------------------------------------------------------------------
// Pre-pass 1: x fp32 -> fp16
// ---------------------------------------------------------------------------
__global__ void __launch_bounds__(256) convert_x_kernel(const float4* __restrict__ x) {
    int i = blockIdx.x * 256 + threadIdx.x;
    float4 v = x[i];
    union { __half2 h[2]; uint2 u; } p;
    p.h[0] = __floats2half2_rn(v.x, v.y);
    p.h[1] = __floats2half2_rn(v.z, v.w);
    ((uint2*)g_xh)[i] = p.u;
}

// ---------------------------------------------------------------------------
// Pre-pass 2: int4 nibble dequant -> fp16 (exact: (q-8) in [-8,7])
// low nibble -> even input index, high nibble -> odd input index
// ---------------------------------------------------------------------------
__device__ __forceinline__ __half2 deq_nib(int v) {
    return __halves2half2(__int2half_rn((v & 0xF) - 8),
                          __int2half_rn(((v >> 4) & 0xF) - 8));
}

__global__ void __launch_bounds__(256) dequant_w_kernel(const int4* __restrict__ wp) {
    int i = blockIdx.x * 256 + threadIdx.x;
    int4 v = wp[i];
    union { __half2 h[4]; uint4 u; } p;
    p.h[0] = deq_nib(v.x); p.h[1] = deq_nib(v.y);
    p.h[2] = deq_nib(v.z); p.h[3] = deq_nib(v.w);
    ((uint4*)g_wh)[i] = p.u;
}

// ---------------------------------------------------------------------------
// Baseline-ISA helpers (no sm_103a-gated instructions!)
// ---------------------------------------------------------------------------
__device__ __forceinline__ uint32_t smem_u32(const void* p) {
    uint32_t a;
    asm("{ .reg .u64 t; cvta.to.shared.u64 t, %1; cvt.u32.u64 %0, t; }" : "=r"(a) : "l"(p));
    return a;
}

#define CP_ASYNC16(sm, gp) \
    asm volatile("cp.async.cg.shared.global [%0], [%1], 16;" :: "r"(sm), "l"(gp) : "memory")
#define CP_COMMIT() asm volatile("cp.async.commit_group;" ::: "memory")
#define CP_WAIT(n)  asm volatile("cp.async.wait_group %0;" :: "n"(n) : "memory")

#define LDSM_X4(r0, r1, r2, r3, addr) \
    asm volatile("ldmatrix.sync.aligned.m8n8.x4.shared.b16 {%0,%1,%2,%3}, [%4];" \
                 : "=r"(r0), "=r"(r1), "=r"(r2), "=r"(r3) : "r"(addr))

#define MMA16816(c, a, b) \
    asm volatile("mma.sync.aligned.m16n8k16.row.col.f32.f16.f16.f32 " \
                 "{%0,%1,%2,%3}, {%4,%5,%6,%7}, {%8,%9}, {%0,%1,%2,%3};" \
                 : "+f"((c)[0]), "+f"((c)[1]), "+f"((c)[2]), "+f"((c)[3]) \
                 : "r"((a)[0]), "r"((a)[1]), "r"((a)[2]), "r"((a)[3]), \
                   "r"((b)[0]), "r"((b)[1]))

// ---------------------------------------------------------------------------
// GEMM: out[N, OUT] = x_h[N, K] @ w_h[OUT, K]^T, epilogue: *scale[o] + bias[o]
// CTA 128x128, BK=64, 4-stage cp.async pipeline, 8 warps of 64x32 HMMA tiles.
// ---------------------------------------------------------------------------
__global__ void __launch_bounds__(256, 1)
gemm_kernel(const float* __restrict__ ws, const float* __restrict__ bs,
            float* __restrict__ out) {
    extern __shared__ char smem[];
    const uint32_t sb = smem_u32(smem);
    const int tid = threadIdx.x, wid = tid >> 5, lane = tid & 31;
    const int wr = wid >> 2, wc = wid & 3;             // warp grid 2(m) x 4(n)
    const int m0 = blockIdx.y * BM, n0 = blockIdx.x * BN;

    // scale/bias for this CTA's 128 output columns
    if (tid < BN)      ((float*)(smem + SMEM_SCALE))[tid]       = ws[n0 + tid];
    else               ((float*)(smem + SMEM_BIAS))[tid - BN]   = bs[n0 + tid - BN];

    // ---- cp.async geometry: each thread copies 4 A chunks + 4 B chunks (16B) ----
    const int ldRow = tid >> 3;                        // 0..31
    const int ldCol = tid & 7;                         // 16B chunk within 128B row
    const int scol  = ldCol ^ (ldRow & 7);             // xor-swizzle (8x16B)
    const __half* gA = g_xh + (size_t)(m0 + ldRow) * DIM + ldCol * 8;
    const __half* gB = g_wh + (size_t)(n0 + ldRow) * DIM + ldCol * 8;
    const uint32_t sA = sb + ldRow * 128 + scol * 16;
    const uint32_t sB = sA + 16384;

#define LOAD_STAGE(k)                                                        \
    {                                                                        \
        uint32_t so = ((k) & (NSTAGE - 1)) * STAGE_BYTES;                    \
        const __half* ga = gA + (size_t)(k) * BK;                            \
        const __half* gb = gB + (size_t)(k) * BK;                            \
        _Pragma("unroll")                                                    \
        for (int i = 0; i < 4; i++) {                                        \
            CP_ASYNC16(sA + so + i * 4096, ga + (size_t)i * 32 * DIM);       \
            CP_ASYNC16(sB + so + i * 4096, gb + (size_t)i * 32 * DIM);       \
        }                                                                    \
    }

    // ---- ldmatrix geometry ----
    // A: lanes 0-7 rows 0-7 @k0 | 8-15 rows 8-15 @k0 | 16-23 rows 0-7 @k8 | 24-31 rows 8-15 @k8
    const int aRow  = wr * 64 + (lane & 15);
    const int bRow  = wc * 32 + (lane & 15);
    const int kHalf = lane >> 4;                       // 0/1 -> +8 halves in k

    float c[4][4][4];
#pragma unroll
    for (int mi = 0; mi < 4; mi++)
#pragma unroll
        for (int ni = 0; ni < 4; ni++)
#pragma unroll
            for (int e = 0; e < 4; e++) c[mi][ni][e] = 0.0f;

    // prologue: fill 3 stages
    LOAD_STAGE(0); CP_COMMIT();
    LOAD_STAGE(1); CP_COMMIT();
    LOAD_STAGE(2); CP_COMMIT();

    for (int k = 0; k < KT; k++) {
        CP_WAIT(2);                 // stage k resident
        __syncthreads();            // visible to all; stage (k-1) compute done by all

        if (k + 3 < KT) LOAD_STAGE(k + 3);
        CP_COMMIT();                // keep group arithmetic uniform (empty ok)

        const uint32_t st = sb + (k & (NSTAGE - 1)) * STAGE_BYTES;
#pragma unroll
        for (int ks = 0; ks < 4; ks++) {
            uint32_t a[4][4], b[4][2];
#pragma unroll
            for (int mi = 0; mi < 4; mi++) {
                int r = aRow + mi * 16;
                uint32_t ch = (uint32_t)((kHalf + ks * 2) ^ (r & 7));
                LDSM_X4(a[mi][0], a[mi][1], a[mi][2], a[mi][3], st + r * 128 + ch * 16);
            }
#pragma unroll
            for (int p = 0; p < 2; p++) {
                int r = bRow + p * 16;
                uint32_t ch = (uint32_t)((kHalf + ks * 2) ^ (r & 7));
                LDSM_X4(b[2 * p][0], b[2 * p + 1][0], b[2 * p][1], b[2 * p + 1][1],
                        st + 16384 + r * 128 + ch * 16);
            }
#pragma unroll
            for (int mi = 0; mi < 4; mi++)
#pragma unroll
                for (int ni = 0; ni < 4; ni++)
                    MMA16816(c[mi][ni], a[mi], b[ni]);
        }
        __syncthreads();            // stage k consumed; its buffer reusable next iters
    }

    // ---- epilogue: scale * acc + bias, fp32 paired stores ----
    const float* ssc = (const float*)(smem + SMEM_SCALE);
    const float* sbi = (const float*)(smem + SMEM_BIAS);
    const int rBase = m0 + wr * 64 + (lane >> 2);
    const int cBase = wc * 32 + (lane & 3) * 2;
#pragma unroll
    for (int mi = 0; mi < 4; mi++) {
#pragma unroll
        for (int ni = 0; ni < 4; ni++) {
            const int col = cBase + ni * 8;
            const float s0 = ssc[col], s1 = ssc[col + 1];
            const float b0 = sbi[col], b1 = sbi[col + 1];
            float* p0 = out + (size_t)(rBase + mi * 16) * DIM + n0 + col;
            float* p1 = p0 + (size_t)8 * DIM;
            float2 v0 = make_float2(c[mi][ni][0] * s0 + b0, c[mi][ni][1] * s1 + b1);
            float2 v1 = make_float2(c[mi][ni][2] * s0 + b0, c[mi][ni][3] * s1 + b1);
            *(float2*)p0 = v0;
            *(float2*)p1 = v1;
        }
    }
}

// ---------------------------------------------------------------------------
// Launch
// ---------------------------------------------------------------------------
extern "C" void kernel_launch(void* const* d_in, const int* in_sizes, int n_in,
                              void* d_out, int out_size) {
    (void)in_sizes; (void)n_in; (void)out_size;
    const float* x    = (const float*)d_in[0];
    const int*   wp   = (const int*)d_in[1];
    const float* ws   = (const float*)d_in[2];
    const float* bias = (const float*)d_in[3];
    float* out = (float*)d_out;

    cudaFuncSetAttribute(gemm_kernel, cudaFuncAttributeMaxDynamicSharedMemorySize, SMEM_BYTES);

    convert_x_kernel<<<(DIM * DIM / 4) / 256, 256>>>((const float4*)x);
    dequant_w_kernel<<<(DIM * (DIM / 2) / 4) / 256, 256>>>((const int4*)wp);
    gemm_kernel<<<dim3(DIM / BN, DIM / BM), 256, SMEM_BYTES>>>(ws, bias, out);
}

// round 3
// speedup vs baseline: 1.5047x; 1.5047x over previous
#include <cuda_runtime.h>
#include <cuda_fp16.h>
#include <cstdint>

#define DIM 4096
#define BM 256
#define BN 128
#define BK 64
#define KT (DIM / BK)            // 64 k-stages
#define NSTAGE 4
#define STAGE_BYTES 49152        // A 256x128B (32KB) + B 128x128B (16KB)
#define SMEM_SCALE (NSTAGE * STAGE_BYTES)
#define SMEM_BIAS  (SMEM_SCALE + BN * 4)
#define SMEM_BYTES (SMEM_BIAS + BN * 4)   // 197632

// fp16 scratch operands (allocation-free: __device__ globals)
__device__ __half g_xh[(size_t)DIM * DIM];
__device__ __half g_wh[(size_t)DIM * DIM];

// ---------------------------------------------------------------------------
// Pre-pass 1: x fp32 -> fp16
// ---------------------------------------------------------------------------
__global__ void __launch_bounds__(256) convert_x_kernel(const float4* __restrict__ x) {
    int i = blockIdx.x * 256 + threadIdx.x;
    float4 v = x[i];
    union { __half2 h[2]; uint2 u; } p;
    p.h[0] = __floats2half2_rn(v.x, v.y);
    p.h[1] = __floats2half2_rn(v.z, v.w);
    ((uint2*)g_xh)[i] = p.u;
}

// ---------------------------------------------------------------------------
// Pre-pass 2: int4 nibble dequant -> fp16 (exact: (q-8) in [-8,7])
// ---------------------------------------------------------------------------
__device__ __forceinline__ __half2 deq_nib(int v) {
    return __halves2half2(__int2half_rn((v & 0xF) - 8),
                          __int2half_rn(((v >> 4) & 0xF) - 8));
}

__global__ void __launch_bounds__(256) dequant_w_kernel(const int4* __restrict__ wp) {
    int i = blockIdx.x * 256 + threadIdx.x;
    int4 v = wp[i];
    union { __half2 h[4]; uint4 u; } p;
    p.h[0] = deq_nib(v.x); p.h[1] = deq_nib(v.y);
    p.h[2] = deq_nib(v.z); p.h[3] = deq_nib(v.w);
    ((uint4*)g_wh)[i] = p.u;
}

// ---------------------------------------------------------------------------
// Baseline-ISA helpers (no sm_103a-gated instructions; ptxas target is sm_103)
// ---------------------------------------------------------------------------
__device__ __forceinline__ uint32_t smem_u32(const void* p) {
    uint32_t a;
    asm("{ .reg .u64 t; cvta.to.shared.u64 t, %1; cvt.u32.u64 %0, t; }" : "=r"(a) : "l"(p));
    return a;
}

#define CP_ASYNC16(sm, gp) \
    asm volatile("cp.async.cg.shared.global [%0], [%1], 16;" :: "r"(sm), "l"(gp) : "memory")
#define CP_COMMIT() asm volatile("cp.async.commit_group;" ::: "memory")
#define CP_WAIT(n)  asm volatile("cp.async.wait_group %0;" :: "n"(n) : "memory")

#define LDSM_X4(r0, r1, r2, r3, addr) \
    asm volatile("ldmatrix.sync.aligned.m8n8.x4.shared.b16 {%0,%1,%2,%3}, [%4];" \
                 : "=r"(r0), "=r"(r1), "=r"(r2), "=r"(r3) : "r"(addr))

#define MMA16816(c, a, b) \
    asm volatile("mma.sync.aligned.m16n8k16.row.col.f32.f16.f16.f32 " \
                 "{%0,%1,%2,%3}, {%4,%5,%6,%7}, {%8,%9}, {%0,%1,%2,%3};" \
                 : "+f"((c)[0]), "+f"((c)[1]), "+f"((c)[2]), "+f"((c)[3]) \
                 : "r"((a)[0]), "r"((a)[1]), "r"((a)[2]), "r"((a)[3]), \
                   "r"((b)[0]), "r"((b)[1]))

// ---------------------------------------------------------------------------
// GEMM: out[N, OUT] = x_h[N, K] @ w_h[OUT, K]^T, epilogue: *scale[o] + bias[o]
// CTA 256x128, BK=64, 4-stage cp.async pipeline, 8 warps of 64x64 HMMA tiles,
// single __syncthreads per k-stage.
// ---------------------------------------------------------------------------
__global__ void __launch_bounds__(256, 1)
gemm_kernel(const float* __restrict__ ws, const float* __restrict__ bs,
            float* __restrict__ out) {
    extern __shared__ char smem[];
    const uint32_t sb = smem_u32(smem);
    const int tid = threadIdx.x, wid = tid >> 5, lane = tid & 31;
    const int wr = wid >> 1, wc = wid & 1;             // warp grid 4(m) x 2(n)
    const int m0 = blockIdx.y * BM, n0 = blockIdx.x * BN;

    // scale/bias for this CTA's 128 output columns
    if (tid < BN)      ((float*)(smem + SMEM_SCALE))[tid]     = ws[n0 + tid];
    else               ((float*)(smem + SMEM_BIAS))[tid - BN] = bs[n0 + tid - BN];

    // ---- cp.async geometry: per thread 8 A chunks + 4 B chunks (16B each) ----
    const int ldRow = tid >> 3;                        // 0..31
    const int ldCol = tid & 7;                         // 16B chunk within 128B row
    const int scol  = ldCol ^ (ldRow & 7);             // xor-swizzle (8x16B)
    const __half* gA = g_xh + (size_t)(m0 + ldRow) * DIM + ldCol * 8;
    const __half* gB = g_wh + (size_t)(n0 + ldRow) * DIM + ldCol * 8;
    const uint32_t sA = sb + ldRow * 128 + scol * 16;
    const uint32_t sB = sA + 32768;

#define LOAD_STAGE(k)                                                        \
    {                                                                        \
        uint32_t so = ((k) & (NSTAGE - 1)) * STAGE_BYTES;                    \
        const __half* ga = gA + (size_t)(k) * BK;                            \
        const __half* gb = gB + (size_t)(k) * BK;                            \
        _Pragma("unroll")                                                    \
        for (int i = 0; i < 8; i++)                                          \
            CP_ASYNC16(sA + so + i * 4096, ga + (size_t)i * 32 * DIM);       \
        _Pragma("unroll")                                                    \
        for (int i = 0; i < 4; i++)                                          \
            CP_ASYNC16(sB + so + i * 4096, gb + (size_t)i * 32 * DIM);       \
    }

    // ---- ldmatrix geometry (identical fragment mapping to the R2 kernel) ----
    const int aRow  = wr * 64 + (lane & 15);
    const int bRow  = wc * 64 + (lane & 15);
    const int kHalf = lane >> 4;

    float c[4][8][4];
#pragma unroll
    for (int mi = 0; mi < 4; mi++)
#pragma unroll
        for (int ni = 0; ni < 8; ni++)
#pragma unroll
            for (int e = 0; e < 4; e++) c[mi][ni][e] = 0.0f;

    // prologue: fill 3 stages
    LOAD_STAGE(0); CP_COMMIT();
    LOAD_STAGE(1); CP_COMMIT();
    LOAD_STAGE(2); CP_COMMIT();

#pragma unroll 1
    for (int k = 0; k < KT; k++) {
        CP_WAIT(2);                 // stage k resident
        __syncthreads();            // also: all threads done with stage k-1 ->
                                    // safe to overwrite slot (k+3)&3 == (k-1)&3

        if (k + 3 < KT) LOAD_STAGE(k + 3);
        CP_COMMIT();                // uniform group count (empty ok at tail)

        const uint32_t st = sb + (k & (NSTAGE - 1)) * STAGE_BYTES;
#pragma unroll
        for (int ks = 0; ks < 4; ks++) {
            uint32_t a[4][4], b[8][2];
#pragma unroll
            for (int mi = 0; mi < 4; mi++) {
                int r = aRow + mi * 16;
                uint32_t ch = (uint32_t)((kHalf + ks * 2) ^ (r & 7));
                LDSM_X4(a[mi][0], a[mi][1], a[mi][2], a[mi][3], st + r * 128 + ch * 16);
            }
#pragma unroll
            for (int p = 0; p < 4; p++) {
                int r = bRow + p * 16;
                uint32_t ch = (uint32_t)((kHalf + ks * 2) ^ (r & 7));
                LDSM_X4(b[2 * p][0], b[2 * p + 1][0], b[2 * p][1], b[2 * p + 1][1],
                        st + 32768 + r * 128 + ch * 16);
            }
#pragma unroll
            for (int mi = 0; mi < 4; mi++)
#pragma unroll
                for (int ni = 0; ni < 8; ni++)
                    MMA16816(c[mi][ni], a[mi], b[ni]);
        }
    }

    // ---- epilogue: scale * acc + bias, fp32 paired stores ----
    const float* ssc = (const float*)(smem + SMEM_SCALE);
    const float* sbi = (const float*)(smem + SMEM_BIAS);
    const int rBase = m0 + wr * 64 + (lane >> 2);
    const int cBase = wc * 64 + (lane & 3) * 2;
#pragma unroll
    for (int mi = 0; mi < 4; mi++) {
#pragma unroll
        for (int ni = 0; ni < 8; ni++) {
            const int col = cBase + ni * 8;
            const float s0 = ssc[col], s1 = ssc[col + 1];
            const float b0 = sbi[col], b1 = sbi[col + 1];
            float* p0 = out + (size_t)(rBase + mi * 16) * DIM + n0 + col;
            float* p1 = p0 + (size_t)8 * DIM;
            *(float2*)p0 = make_float2(c[mi][ni][0] * s0 + b0, c[mi][ni][1] * s1 + b1);
            *(float2*)p1 = make_float2(c[mi][ni][2] * s0 + b0, c[mi][ni][3] * s1 + b1);
        }
    }
}

// ---------------------------------------------------------------------------
// Launch
// ---------------------------------------------------------------------------
extern "C" void kernel_launch(void* const* d_in, const int* in_sizes, int n_in,
                              void* d_out, int out_size) {
    (void)in_sizes; (void)n_in; (void)out_size;
    const float* x    = (const float*)d_in[0];
    const int*   wp   = (const int*)d_in[1];
    const float* ws   = (const float*)d_in[2];
    const float* bias = (const float*)d_in[3];
    float* out = (float*)d_out;

    cudaFuncSetAttribute(gemm_kernel, cudaFuncAttributeMaxDynamicSharedMemorySize, SMEM_BYTES);

    convert_x_kernel<<<(DIM * DIM / 4) / 256, 256>>>((const float4*)x);
    dequant_w_kernel<<<(DIM * (DIM / 2) / 4) / 256, 256>>>((const int4*)wp);
    gemm_kernel<<<dim3(DIM / BN, DIM / BM), 256, SMEM_BYTES>>>(ws, bias, out);
}

// round 4
// speedup vs baseline: 1.7324x; 1.1513x over previous
#include <cuda_runtime.h>
#include <cuda_fp16.h>
#include <cstdint>

#define DIM 4096
#define BM 128
#define BN 128
#define BK 64
#define KT (DIM / BK)            // 64 k-stages
#define NSTAGE 3
#define STAGE_BYTES 32768        // A 128x128B (16KB) + B 128x128B (16KB)
#define SMEM_SCALE (NSTAGE * STAGE_BYTES)
#define SMEM_BIAS  (SMEM_SCALE + BN * 4)
#define SMEM_BYTES (SMEM_BIAS + BN * 4)   // 99328 -> occ 2 (<=113KB/CTA)

// fp16 scratch operands (allocation-free: __device__ globals)
__device__ __half g_xh[(size_t)DIM * DIM];
__device__ __half g_wh[(size_t)DIM * DIM];

// ---------------------------------------------------------------------------
// Fused pre-pass: blocks [0, 16384) convert x fp32->fp16,
//                 blocks [16384, 24576) dequant w int4 nibbles -> fp16 (exact)
// ---------------------------------------------------------------------------
__device__ __forceinline__ __half2 deq_nib(int v) {
    return __halves2half2(__int2half_rn((v & 0xF) - 8),
                          __int2half_rn(((v >> 4) & 0xF) - 8));
}

__global__ void __launch_bounds__(256) prep_kernel(const float4* __restrict__ x,
                                                   const int4* __restrict__ wp) {
    int b = blockIdx.x;
    if (b < 16384) {
        int i = b * 256 + threadIdx.x;
        float4 v = x[i];
        union { __half2 h[2]; uint2 u; } p;
        p.h[0] = __floats2half2_rn(v.x, v.y);
        p.h[1] = __floats2half2_rn(v.z, v.w);
        ((uint2*)g_xh)[i] = p.u;
    } else {
        int i = (b - 16384) * 256 + threadIdx.x;
        int4 v = wp[i];
        union { __half2 h[4]; uint4 u; } p;
        p.h[0] = deq_nib(v.x); p.h[1] = deq_nib(v.y);
        p.h[2] = deq_nib(v.z); p.h[3] = deq_nib(v.w);
        ((uint4*)g_wh)[i] = p.u;
    }
}

// ---------------------------------------------------------------------------
// Baseline-ISA helpers (ptxas target is plain sm_103: no tcgen05/TMA)
// ---------------------------------------------------------------------------
__device__ __forceinline__ uint32_t smem_u32(const void* p) {
    uint32_t a;
    asm("{ .reg .u64 t; cvta.to.shared.u64 t, %1; cvt.u32.u64 %0, t; }" : "=r"(a) : "l"(p));
    return a;
}

#define CP_ASYNC16(sm, gp) \
    asm volatile("cp.async.cg.shared.global [%0], [%1], 16;" :: "r"(sm), "l"(gp) : "memory")
#define CP_COMMIT() asm volatile("cp.async.commit_group;" ::: "memory")
#define CP_WAIT(n)  asm volatile("cp.async.wait_group %0;" :: "n"(n) : "memory")

#define LDSM_X4(r0, r1, r2, r3, addr) \
    asm volatile("ldmatrix.sync.aligned.m8n8.x4.shared.b16 {%0,%1,%2,%3}, [%4];" \
                 : "=r"(r0), "=r"(r1), "=r"(r2), "=r"(r3) : "r"(addr))

#define MMA16816(c, a, b) \
    asm volatile("mma.sync.aligned.m16n8k16.row.col.f32.f16.f16.f32 " \
                 "{%0,%1,%2,%3}, {%4,%5,%6,%7}, {%8,%9}, {%0,%1,%2,%3};" \
                 : "+f"((c)[0]), "+f"((c)[1]), "+f"((c)[2]), "+f"((c)[3]) \
                 : "r"((a)[0]), "r"((a)[1]), "r"((a)[2]), "r"((a)[3]), \
                   "r"((b)[0]), "r"((b)[1]))

// ---------------------------------------------------------------------------
// GEMM: out[N, OUT] = x_h[N, K] @ w_h[OUT, K]^T, epilogue: *scale[o] + bias[o]
// CTA 128x128, BK=64, 3-stage cp.async pipeline, occupancy 2,
// 8 warps of 64x32 HMMA tiles, single __syncthreads per k-stage.
// ---------------------------------------------------------------------------
__global__ void __launch_bounds__(256, 2)
gemm_kernel(const float* __restrict__ ws, const float* __restrict__ bs,
            float* __restrict__ out) {
    extern __shared__ char smem[];
    const uint32_t sb = smem_u32(smem);
    const int tid = threadIdx.x, wid = tid >> 5, lane = tid & 31;
    const int wr = wid >> 2, wc = wid & 3;             // warp grid 2(m) x 4(n)
    const int m0 = blockIdx.y * BM, n0 = blockIdx.x * BN;

    // scale/bias for this CTA's 128 output columns
    if (tid < BN)      ((float*)(smem + SMEM_SCALE))[tid]     = ws[n0 + tid];
    else               ((float*)(smem + SMEM_BIAS))[tid - BN] = bs[n0 + tid - BN];

    // ---- cp.async geometry: per thread 4 A chunks + 4 B chunks (16B each) ----
    const int ldRow = tid >> 3;                        // 0..31
    const int ldCol = tid & 7;                         // 16B chunk within 128B row
    const int scol  = ldCol ^ (ldRow & 7);             // xor-swizzle (8x16B)
    const __half* gA = g_xh + (size_t)(m0 + ldRow) * DIM + ldCol * 8;
    const __half* gB = g_wh + (size_t)(n0 + ldRow) * DIM + ldCol * 8;
    const uint32_t sA = sb + ldRow * 128 + scol * 16;
    const uint32_t sB = sA + 16384;

#define LOAD_STAGE(k)                                                        \
    {                                                                        \
        uint32_t so = ((k) % NSTAGE) * STAGE_BYTES;                          \
        const __half* ga = gA + (size_t)(k) * BK;                            \
        const __half* gb = gB + (size_t)(k) * BK;                            \
        _Pragma("unroll")                                                    \
        for (int i = 0; i < 4; i++) {                                        \
            CP_ASYNC16(sA + so + i * 4096, ga + (size_t)i * 32 * DIM);       \
            CP_ASYNC16(sB + so + i * 4096, gb + (size_t)i * 32 * DIM);       \
        }                                                                    \
    }

    // ---- ldmatrix geometry ----
    const int aRow  = wr * 64 + (lane & 15);
    const int bRow  = wc * 32 + (lane & 15);
    const int kHalf = lane >> 4;

    float c[4][4][4];
#pragma unroll
    for (int mi = 0; mi < 4; mi++)
#pragma unroll
        for (int ni = 0; ni < 4; ni++)
#pragma unroll
            for (int e = 0; e < 4; e++) c[mi][ni][e] = 0.0f;

    // prologue: fill 2 stages
    LOAD_STAGE(0); CP_COMMIT();
    LOAD_STAGE(1); CP_COMMIT();

#pragma unroll 1
    for (int k = 0; k < KT; k++) {
        CP_WAIT(1);                 // stage k resident (<=1 group pending)
        __syncthreads();            // all threads done with stage k-1 ->
                                    // safe to overwrite slot (k+2)%3

        if (k + 2 < KT) LOAD_STAGE(k + 2);
        CP_COMMIT();                // uniform group count (empty ok at tail)

        const uint32_t st = sb + (k % NSTAGE) * STAGE_BYTES;
#pragma unroll
        for (int ks = 0; ks < 4; ks++) {
            uint32_t a[4][4], b[4][2];
#pragma unroll
            for (int mi = 0; mi < 4; mi++) {
                int r = aRow + mi * 16;
                uint32_t ch = (uint32_t)((kHalf + ks * 2) ^ (r & 7));
                LDSM_X4(a[mi][0], a[mi][1], a[mi][2], a[mi][3], st + r * 128 + ch * 16);
            }
#pragma unroll
            for (int p = 0; p < 2; p++) {
                int r = bRow + p * 16;
                uint32_t ch = (uint32_t)((kHalf + ks * 2) ^ (r & 7));
                LDSM_X4(b[2 * p][0], b[2 * p + 1][0], b[2 * p][1], b[2 * p + 1][1],
                        st + 16384 + r * 128 + ch * 16);
            }
#pragma unroll
            for (int mi = 0; mi < 4; mi++)
#pragma unroll
                for (int ni = 0; ni < 4; ni++)
                    MMA16816(c[mi][ni], a[mi], b[ni]);
        }
    }

    // ---- epilogue: scale * acc + bias, fp32 paired stores ----
    const float* ssc = (const float*)(smem + SMEM_SCALE);
    const float* sbi = (const float*)(smem + SMEM_BIAS);
    const int rBase = m0 + wr * 64 + (lane >> 2);
    const int cBase = wc * 32 + (lane & 3) * 2;
#pragma unroll
    for (int mi = 0; mi < 4; mi++) {
#pragma unroll
        for (int ni = 0; ni < 4; ni++) {
            const int col = cBase + ni * 8;
            const float s0 = ssc[col], s1 = ssc[col + 1];
            const float b0 = sbi[col], b1 = sbi[col + 1];
            float* p0 = out + (size_t)(rBase + mi * 16) * DIM + n0 + col;
            float* p1 = p0 + (size_t)8 * DIM;
            *(float2*)p0 = make_float2(c[mi][ni][0] * s0 + b0, c[mi][ni][1] * s1 + b1);
            *(float2*)p1 = make_float2(c[mi][ni][2] * s0 + b0, c[mi][ni][3] * s1 + b1);
        }
    }
}

// ---------------------------------------------------------------------------
// Launch
// ---------------------------------------------------------------------------
extern "C" void kernel_launch(void* const* d_in, const int* in_sizes, int n_in,
                              void* d_out, int out_size) {
    (void)in_sizes; (void)n_in; (void)out_size;
    const float* x    = (const float*)d_in[0];
    const int*   wp   = (const int*)d_in[1];
    const float* ws   = (const float*)d_in[2];
    const float* bias = (const float*)d_in[3];
    float* out = (float*)d_out;

    cudaFuncSetAttribute(gemm_kernel, cudaFuncAttributeMaxDynamicSharedMemorySize, SMEM_BYTES);

    prep_kernel<<<16384 + 8192, 256>>>((const float4*)x, (const int4*)wp);
    gemm_kernel<<<dim3(DIM / BN, DIM / BM), 256, SMEM_BYTES>>>(ws, bias, out);
}